// round 1
// baseline (speedup 1.0000x reference)
#include <cuda_runtime.h>
#include <math.h>

#define NN 50000
#define NE 640000
#define DH 128
#define NG 1024
#define NL 3
#define BN_EPS 1e-5f

// ---------------- scratch (device globals; no allocation allowed) ----------
__device__ int   g_deg[NN];
__device__ int   g_off[NN + 1];
__device__ int   g_cur[NN];
__device__ float g_dinv[NN];
__device__ int   g_csr[NE];
__device__ float g_gbuf[(size_t)NN * DH];   // g = dinv * (A' @ W)
__device__ float g_hag[(size_t)NN * DH];    // aggregated h (pre-BN)
__device__ float g_sum[NL * DH];
__device__ float g_sq[NL * DH];
__device__ float g_scale[NL * DH];
__device__ float g_shift[NL * DH];
__device__ int   g_cnt[NG];

__device__ __forceinline__ float elu1(float v) {
    return v > 0.f ? v : (expf(v) - 1.f);
}

// ---------------- preprocessing ----------------
__global__ void k_init() {
    int i = blockIdx.x * blockDim.x + threadIdx.x;
    if (i < NN) g_deg[i] = 0;
    if (i < NL * DH) { g_sum[i] = 0.f; g_sq[i] = 0.f; }
    if (i < NG) g_cnt[i] = 0;
}

__global__ void k_deg(const int* __restrict__ dst) {
    int e = blockIdx.x * blockDim.x + threadIdx.x;
    if (e < NE) atomicAdd(&g_deg[dst[e]], 1);
}

__global__ void k_dinv() {
    int i = blockIdx.x * blockDim.x + threadIdx.x;
    if (i < NN) g_dinv[i] = rsqrtf((float)(g_deg[i] + 1));  // +1 self loop
}

// single-block exclusive scan of g_deg -> g_off (and g_cur)
__global__ void k_scan() {
    __shared__ int smem[1024];
    __shared__ int carry;
    int tid = threadIdx.x;
    if (tid == 0) carry = 0;
    __syncthreads();
    for (int base = 0; base < NN; base += 1024) {
        int i = base + tid;
        int v = (i < NN) ? g_deg[i] : 0;
        smem[tid] = v;
        __syncthreads();
        #pragma unroll
        for (int d = 1; d < 1024; d <<= 1) {
            int t = (tid >= d) ? smem[tid - d] : 0;
            __syncthreads();
            smem[tid] += t;
            __syncthreads();
        }
        int excl = smem[tid] - v + carry;
        if (i < NN) { g_off[i] = excl; g_cur[i] = excl; }
        __syncthreads();
        if (tid == 1023) carry += smem[1023];
        __syncthreads();
    }
    if (tid == 0) g_off[NN] = carry;
}

__global__ void k_fill(const int* __restrict__ src, const int* __restrict__ dst) {
    int e = blockIdx.x * blockDim.x + threadIdx.x;
    if (e < NE) {
        int d = dst[e];
        int pos = atomicAdd(&g_cur[d], 1);
        g_csr[pos] = src[e];
    }
}

// ---------------- GEMM: g = dinv * (A' @ W), A' = (layer>0 ? elu(BN(A)) : A)
// BM=BN=128, BK=16, 256 threads, 8x8 per thread
__global__ void __launch_bounds__(256) k_gemm(int layer,
                                              const float* __restrict__ x,
                                              const float* __restrict__ W) {
    __shared__ float As[16][132];
    __shared__ float Bs[16][128];
    const float* A = (layer == 0) ? x : g_hag;
    const float* sc = g_scale + (layer > 0 ? (layer - 1) * DH : 0);
    const float* sh = g_shift + (layer > 0 ? (layer - 1) * DH : 0);

    int tid = threadIdx.x;
    int row0 = blockIdx.x * 128;
    int tx = tid & 15, ty = tid >> 4;
    float acc[8][8];
    #pragma unroll
    for (int i = 0; i < 8; ++i)
        #pragma unroll
        for (int j = 0; j < 8; ++j) acc[i][j] = 0.f;

    for (int k0 = 0; k0 < DH; k0 += 16) {
        // A tile: 128 rows x 16 cols (transform + transpose into As[k][m])
        #pragma unroll
        for (int i = 0; i < 2; ++i) {
            int idx = tid * 2 + i;
            int r = idx >> 2;
            int c4 = idx & 3;
            int gr = row0 + r;
            float4 v = make_float4(0.f, 0.f, 0.f, 0.f);
            if (gr < NN) v = *(const float4*)(A + (size_t)gr * DH + k0 + c4 * 4);
            float vv[4] = {v.x, v.y, v.z, v.w};
            #pragma unroll
            for (int j = 0; j < 4; ++j) {
                float f = vv[j];
                if (layer > 0) {
                    int kk = k0 + c4 * 4 + j;
                    f = fmaf(f, sc[kk], sh[kk]);
                    f = elu1(f);
                }
                As[c4 * 4 + j][r] = f;
            }
        }
        // W tile: 16 rows x 128 cols
        #pragma unroll
        for (int i = 0; i < 2; ++i) {
            int idx = tid * 2 + i;
            int r = idx >> 5;
            int c4 = idx & 31;
            float4 v = *(const float4*)(W + (size_t)(k0 + r) * DH + c4 * 4);
            *(float4*)&Bs[r][c4 * 4] = v;
        }
        __syncthreads();
        #pragma unroll
        for (int kk = 0; kk < 16; ++kk) {
            float a[8], b[8];
            *(float4*)&a[0] = *(const float4*)&As[kk][ty * 8];
            *(float4*)&a[4] = *(const float4*)&As[kk][ty * 8 + 4];
            *(float4*)&b[0] = *(const float4*)&Bs[kk][tx * 8];
            *(float4*)&b[4] = *(const float4*)&Bs[kk][tx * 8 + 4];
            #pragma unroll
            for (int i = 0; i < 8; ++i)
                #pragma unroll
                for (int j = 0; j < 8; ++j)
                    acc[i][j] = fmaf(a[i], b[j], acc[i][j]);
        }
        __syncthreads();
    }
    // epilogue: scale row by dinv, write g
    #pragma unroll
    for (int i = 0; i < 8; ++i) {
        int gr = row0 + ty * 8 + i;
        if (gr < NN) {
            float di = g_dinv[gr];
            #pragma unroll
            for (int j = 0; j < 8; j += 4) {
                float4 o;
                o.x = di * acc[i][j];
                o.y = di * acc[i][j + 1];
                o.z = di * acc[i][j + 2];
                o.w = di * acc[i][j + 3];
                *(float4*)(g_gbuf + (size_t)gr * DH + tx * 8 + j) = o;
            }
        }
    }
}

// ---------------- aggregation: h[i] = dinv[i]*(g[i] + sum g[src]) + b
// one warp per node, float4 per lane; also accumulates BN column stats
__global__ void __launch_bounds__(256) k_agg(int layer, const float* __restrict__ bias) {
    __shared__ float s_sum[DH];
    __shared__ float s_sq[DH];
    int tid = threadIdx.x;
    if (tid < DH) { s_sum[tid] = 0.f; s_sq[tid] = 0.f; }
    __syncthreads();

    int node = blockIdx.x * 8 + (tid >> 5);
    int lane = tid & 31;
    if (node < NN) {
        float4 a0 = *(const float4*)(g_gbuf + (size_t)node * DH + lane * 4);
        float4 a1 = make_float4(0.f, 0.f, 0.f, 0.f);
        int s = g_off[node], e2 = g_off[node + 1];
        int p = s;
        for (; p + 1 < e2; p += 2) {
            int s0 = g_csr[p];
            int s1 = g_csr[p + 1];
            float4 v0 = *(const float4*)(g_gbuf + (size_t)s0 * DH + lane * 4);
            float4 v1 = *(const float4*)(g_gbuf + (size_t)s1 * DH + lane * 4);
            a0.x += v0.x; a0.y += v0.y; a0.z += v0.z; a0.w += v0.w;
            a1.x += v1.x; a1.y += v1.y; a1.z += v1.z; a1.w += v1.w;
        }
        if (p < e2) {
            int s0 = g_csr[p];
            float4 v0 = *(const float4*)(g_gbuf + (size_t)s0 * DH + lane * 4);
            a0.x += v0.x; a0.y += v0.y; a0.z += v0.z; a0.w += v0.w;
        }
        float di = g_dinv[node];
        float4 b = ((const float4*)bias)[lane];
        float4 h;
        h.x = fmaf(di, a0.x + a1.x, b.x);
        h.y = fmaf(di, a0.y + a1.y, b.y);
        h.z = fmaf(di, a0.z + a1.z, b.z);
        h.w = fmaf(di, a0.w + a1.w, b.w);
        *(float4*)(g_hag + (size_t)node * DH + lane * 4) = h;

        int f = lane * 4;
        atomicAdd(&s_sum[f + 0], h.x); atomicAdd(&s_sq[f + 0], h.x * h.x);
        atomicAdd(&s_sum[f + 1], h.y); atomicAdd(&s_sq[f + 1], h.y * h.y);
        atomicAdd(&s_sum[f + 2], h.z); atomicAdd(&s_sq[f + 2], h.z * h.z);
        atomicAdd(&s_sum[f + 3], h.w); atomicAdd(&s_sq[f + 3], h.w * h.w);
    }
    __syncthreads();
    if (tid < DH) {
        atomicAdd(&g_sum[layer * DH + tid], s_sum[tid]);
        atomicAdd(&g_sq[layer * DH + tid], s_sq[tid]);
    }
}

// ---------------- BN finalize: scale = gamma*rsqrt(var+eps), shift = beta - mu*scale
__global__ void k_fin(int layer, const float* __restrict__ gamma,
                      const float* __restrict__ beta) {
    int h = threadIdx.x;  // 128
    float m = g_sum[layer * DH + h] * (1.f / NN);
    float var = g_sq[layer * DH + h] * (1.f / NN) - m * m;
    float rs = rsqrtf(var + BN_EPS);
    float sc = gamma[h] * rs;
    g_scale[layer * DH + h] = sc;
    g_shift[layer * DH + h] = beta[h] - m * sc;
}

// ---------------- pooling ----------------
__global__ void k_count(const int* __restrict__ bidx) {
    int i = blockIdx.x * blockDim.x + threadIdx.x;
    if (i < NN) atomicAdd(&g_cnt[bidx[i]], 1);
}

__global__ void __launch_bounds__(256) k_pool(const int* __restrict__ bidx,
                                              float* __restrict__ out) {
    int tid = threadIdx.x;
    int node = blockIdx.x * 8 + (tid >> 5);
    int lane = tid & 31;
    if (node >= NN) return;
    const int L2 = (NL - 1) * DH;
    float4 h = *(const float4*)(g_hag + (size_t)node * DH + lane * 4);
    int f = lane * 4;
    float v0 = elu1(fmaf(h.x, g_scale[L2 + f + 0], g_shift[L2 + f + 0]));
    float v1 = elu1(fmaf(h.y, g_scale[L2 + f + 1], g_shift[L2 + f + 1]));
    float v2 = elu1(fmaf(h.z, g_scale[L2 + f + 2], g_shift[L2 + f + 2]));
    float v3 = elu1(fmaf(h.w, g_scale[L2 + f + 3], g_shift[L2 + f + 3]));
    int gi = bidx[node];
    float* o = out + (size_t)gi * DH + f;
    atomicAdd(o + 0, v0);
    atomicAdd(o + 1, v1);
    atomicAdd(o + 2, v2);
    atomicAdd(o + 3, v3);
}

__global__ void k_div(float* __restrict__ out) {
    int i = blockIdx.x * blockDim.x + threadIdx.x;
    if (i < NG * DH) {
        float c = (float)g_cnt[i >> 7];
        out[i] = out[i] / fmaxf(c, 1.f);
    }
}

// ---------------- launch ----------------
extern "C" void kernel_launch(void* const* d_in, const int* in_sizes, int n_in,
                              void* d_out, int out_size) {
    const float* x      = (const float*)d_in[0];
    const float* Ws     = (const float*)d_in[1];
    const float* bs     = (const float*)d_in[2];
    const float* gammas = (const float*)d_in[3];
    const float* betas  = (const float*)d_in[4];
    const int*   ei     = (const int*)d_in[5];
    const int*   bidx   = (const int*)d_in[6];
    float*       out    = (float*)d_out;

    const int* src = ei;
    const int* dst = ei + NE;

    k_init<<<(NN + 255) / 256, 256>>>();
    k_deg<<<(NE + 255) / 256, 256>>>(dst);
    k_dinv<<<(NN + 255) / 256, 256>>>();
    k_scan<<<1, 1024>>>();
    k_fill<<<(NE + 255) / 256, 256>>>(src, dst);

    int gemm_grid = (NN + 127) / 128;
    int agg_grid = (NN + 7) / 8;
    for (int l = 0; l < NL; ++l) {
        k_gemm<<<gemm_grid, 256>>>(l, x, Ws + (size_t)l * DH * DH);
        k_agg<<<agg_grid, 256>>>(l, bs + l * DH);
        k_fin<<<1, DH>>>(l, gammas + l * DH, betas + l * DH);
    }

    cudaMemsetAsync(d_out, 0, (size_t)NG * DH * sizeof(float));
    k_count<<<(NN + 255) / 256, 256>>>(bidx);
    k_pool<<<agg_grid, 256>>>(bidx, out);
    k_div<<<(NG * DH + 255) / 256, 256>>>(out);
}

// round 2
// speedup vs baseline: 1.2157x; 1.2157x over previous
#include <cuda_runtime.h>
#include <math.h>

#define NN 50000
#define NE 640000
#define DH 128
#define NG 1024
#define NL 3
#define BN_EPS 1e-5f

#define SCAN_T 256
#define SCAN_NB ((NN + SCAN_T - 1) / SCAN_T)   // 196

// ---------------- scratch (device globals; no allocation allowed) ----------
__device__ int   g_deg[NN];
__device__ int   g_off[NN + 1];
__device__ int   g_cur[NN];
__device__ float g_dinv[NN];
__device__ int   g_csr[NE];
__device__ int   g_bsum[SCAN_NB];
__device__ int   g_boff[SCAN_NB];
__device__ float g_gbuf[(size_t)NN * DH];   // g = dinv * (A' @ W)
__device__ float g_hag[(size_t)NN * DH];    // aggregated h (pre-BN)
__device__ float g_sum[NL * DH];
__device__ float g_sq[NL * DH];
__device__ float g_scale[NL * DH];
__device__ float g_shift[NL * DH];
__device__ int   g_cnt[NG];

__device__ __forceinline__ float elu1(float v) {
    return v > 0.f ? v : (expf(v) - 1.f);
}

// ---------------- preprocessing ----------------
__global__ void k_init() {
    int i = blockIdx.x * blockDim.x + threadIdx.x;
    if (i < NN) g_deg[i] = 0;
    if (i < NL * DH) { g_sum[i] = 0.f; g_sq[i] = 0.f; }
    if (i < NG) g_cnt[i] = 0;
}

__global__ void k_deg(const int* __restrict__ dst) {
    int e = blockIdx.x * blockDim.x + threadIdx.x;
    if (e < NE) atomicAdd(&g_deg[dst[e]], 1);
}

// ---- scan pass 1: per-block sums of g_deg
__global__ void __launch_bounds__(SCAN_T) k_bsum() {
    int i = blockIdx.x * SCAN_T + threadIdx.x;
    int v = (i < NN) ? g_deg[i] : 0;
    #pragma unroll
    for (int o = 16; o; o >>= 1) v += __shfl_down_sync(0xffffffffu, v, o);
    __shared__ int ws[SCAN_T / 32];
    if ((threadIdx.x & 31) == 0) ws[threadIdx.x >> 5] = v;
    __syncthreads();
    if (threadIdx.x < SCAN_T / 32) {
        int s = ws[threadIdx.x];
        #pragma unroll
        for (int o = SCAN_T / 64; o; o >>= 1) s += __shfl_down_sync(0xffu, s, o);
        if (threadIdx.x == 0) g_bsum[blockIdx.x] = s;
    }
}

// ---- scan pass 2: exclusive scan of SCAN_NB block sums (single block of 256)
__global__ void __launch_bounds__(256) k_bscan() {
    int tid = threadIdx.x;
    int lane = tid & 31, wid = tid >> 5;
    int v = (tid < SCAN_NB) ? g_bsum[tid] : 0;
    int incl = v;
    #pragma unroll
    for (int o = 1; o < 32; o <<= 1) {
        int t = __shfl_up_sync(0xffffffffu, incl, o);
        if (lane >= o) incl += t;
    }
    __shared__ int wtot[8];
    if (lane == 31) wtot[wid] = incl;
    __syncthreads();
    if (tid < 8) {
        int s = wtot[tid];
        int si = s;
        #pragma unroll
        for (int o = 1; o < 8; o <<= 1) {
            int t = __shfl_up_sync(0xffu, si, o);
            if (tid >= o) si += t;
        }
        wtot[tid] = si - s;  // exclusive warp prefix
    }
    __syncthreads();
    incl += wtot[wid];
    if (tid < SCAN_NB) g_boff[tid] = incl - v;
    if (tid == 255) g_off[NN] = incl;   // total
}

// ---- scan pass 3: local scan + block offset; also dinv
__global__ void __launch_bounds__(SCAN_T) k_lscan() {
    int tid = threadIdx.x;
    int lane = tid & 31, wid = tid >> 5;
    int i = blockIdx.x * SCAN_T + tid;
    int v = (i < NN) ? g_deg[i] : 0;
    int incl = v;
    #pragma unroll
    for (int o = 1; o < 32; o <<= 1) {
        int t = __shfl_up_sync(0xffffffffu, incl, o);
        if (lane >= o) incl += t;
    }
    __shared__ int wtot[SCAN_T / 32];
    if (lane == 31) wtot[wid] = incl;
    __syncthreads();
    if (tid < SCAN_T / 32) {
        int s = wtot[tid];
        int si = s;
        #pragma unroll
        for (int o = 1; o < SCAN_T / 32; o <<= 1) {
            int t = __shfl_up_sync(0xffu, si, o);
            if (tid >= o) si += t;
        }
        wtot[tid] = si - s;
    }
    __syncthreads();
    int excl = incl - v + wtot[wid] + g_boff[blockIdx.x];
    if (i < NN) {
        g_off[i] = excl;
        g_cur[i] = excl;
        g_dinv[i] = rsqrtf((float)(v + 1));   // +1 self loop
    }
}

__global__ void k_fill(const int* __restrict__ src, const int* __restrict__ dst) {
    int e = blockIdx.x * blockDim.x + threadIdx.x;
    if (e < NE) {
        int d = dst[e];
        int pos = atomicAdd(&g_cur[d], 1);
        g_csr[pos] = src[e];
    }
}

// ---------------- GEMM: g = dinv * (A' @ W), A' = (layer>0 ? elu(BN(A)) : A)
// BM=BN=128, BK=16, 256 threads, 8x8 per thread
__global__ void __launch_bounds__(256) k_gemm(int layer,
                                              const float* __restrict__ x,
                                              const float* __restrict__ W) {
    __shared__ float As[16][132];
    __shared__ float Bs[16][128];
    const float* A = (layer == 0) ? x : g_hag;
    const float* sc = g_scale + (layer > 0 ? (layer - 1) * DH : 0);
    const float* sh = g_shift + (layer > 0 ? (layer - 1) * DH : 0);

    int tid = threadIdx.x;
    int row0 = blockIdx.x * 128;
    int tx = tid & 15, ty = tid >> 4;
    float acc[8][8];
    #pragma unroll
    for (int i = 0; i < 8; ++i)
        #pragma unroll
        for (int j = 0; j < 8; ++j) acc[i][j] = 0.f;

    for (int k0 = 0; k0 < DH; k0 += 16) {
        #pragma unroll
        for (int i = 0; i < 2; ++i) {
            int idx = tid * 2 + i;
            int r = idx >> 2;
            int c4 = idx & 3;
            int gr = row0 + r;
            float4 v = make_float4(0.f, 0.f, 0.f, 0.f);
            if (gr < NN) v = *(const float4*)(A + (size_t)gr * DH + k0 + c4 * 4);
            float vv[4] = {v.x, v.y, v.z, v.w};
            #pragma unroll
            for (int j = 0; j < 4; ++j) {
                float f = vv[j];
                if (layer > 0) {
                    int kk = k0 + c4 * 4 + j;
                    f = fmaf(f, sc[kk], sh[kk]);
                    f = elu1(f);
                }
                As[c4 * 4 + j][r] = f;
            }
        }
        #pragma unroll
        for (int i = 0; i < 2; ++i) {
            int idx = tid * 2 + i;
            int r = idx >> 5;
            int c4 = idx & 31;
            float4 v = *(const float4*)(W + (size_t)(k0 + r) * DH + c4 * 4);
            *(float4*)&Bs[r][c4 * 4] = v;
        }
        __syncthreads();
        #pragma unroll
        for (int kk = 0; kk < 16; ++kk) {
            float a[8], b[8];
            *(float4*)&a[0] = *(const float4*)&As[kk][ty * 8];
            *(float4*)&a[4] = *(const float4*)&As[kk][ty * 8 + 4];
            *(float4*)&b[0] = *(const float4*)&Bs[kk][tx * 8];
            *(float4*)&b[4] = *(const float4*)&Bs[kk][tx * 8 + 4];
            #pragma unroll
            for (int i = 0; i < 8; ++i)
                #pragma unroll
                for (int j = 0; j < 8; ++j)
                    acc[i][j] = fmaf(a[i], b[j], acc[i][j]);
        }
        __syncthreads();
    }
    #pragma unroll
    for (int i = 0; i < 8; ++i) {
        int gr = row0 + ty * 8 + i;
        if (gr < NN) {
            float di = g_dinv[gr];
            #pragma unroll
            for (int j = 0; j < 8; j += 4) {
                float4 o;
                o.x = di * acc[i][j];
                o.y = di * acc[i][j + 1];
                o.z = di * acc[i][j + 2];
                o.w = di * acc[i][j + 3];
                *(float4*)(g_gbuf + (size_t)gr * DH + tx * 8 + j) = o;
            }
        }
    }
}

// ---------------- aggregation: h[i] = dinv[i]*(g[i] + sum g[src]) + b
__global__ void __launch_bounds__(256) k_agg(int layer, const float* __restrict__ bias) {
    __shared__ float s_sum[DH];
    __shared__ float s_sq[DH];
    int tid = threadIdx.x;
    if (tid < DH) { s_sum[tid] = 0.f; s_sq[tid] = 0.f; }
    __syncthreads();

    int node = blockIdx.x * 8 + (tid >> 5);
    int lane = tid & 31;
    if (node < NN) {
        float4 a0 = *(const float4*)(g_gbuf + (size_t)node * DH + lane * 4);
        float4 a1 = make_float4(0.f, 0.f, 0.f, 0.f);
        int s = g_off[node], e2 = g_off[node + 1];
        int p = s;
        for (; p + 1 < e2; p += 2) {
            int s0 = g_csr[p];
            int s1 = g_csr[p + 1];
            float4 v0 = *(const float4*)(g_gbuf + (size_t)s0 * DH + lane * 4);
            float4 v1 = *(const float4*)(g_gbuf + (size_t)s1 * DH + lane * 4);
            a0.x += v0.x; a0.y += v0.y; a0.z += v0.z; a0.w += v0.w;
            a1.x += v1.x; a1.y += v1.y; a1.z += v1.z; a1.w += v1.w;
        }
        if (p < e2) {
            int s0 = g_csr[p];
            float4 v0 = *(const float4*)(g_gbuf + (size_t)s0 * DH + lane * 4);
            a0.x += v0.x; a0.y += v0.y; a0.z += v0.z; a0.w += v0.w;
        }
        float di = g_dinv[node];
        float4 b = ((const float4*)bias)[lane];
        float4 h;
        h.x = fmaf(di, a0.x + a1.x, b.x);
        h.y = fmaf(di, a0.y + a1.y, b.y);
        h.z = fmaf(di, a0.z + a1.z, b.z);
        h.w = fmaf(di, a0.w + a1.w, b.w);
        *(float4*)(g_hag + (size_t)node * DH + lane * 4) = h;

        int f = lane * 4;
        atomicAdd(&s_sum[f + 0], h.x); atomicAdd(&s_sq[f + 0], h.x * h.x);
        atomicAdd(&s_sum[f + 1], h.y); atomicAdd(&s_sq[f + 1], h.y * h.y);
        atomicAdd(&s_sum[f + 2], h.z); atomicAdd(&s_sq[f + 2], h.z * h.z);
        atomicAdd(&s_sum[f + 3], h.w); atomicAdd(&s_sq[f + 3], h.w * h.w);
    }
    __syncthreads();
    if (tid < DH) {
        atomicAdd(&g_sum[layer * DH + tid], s_sum[tid]);
        atomicAdd(&g_sq[layer * DH + tid], s_sq[tid]);
    }
}

// ---------------- BN finalize ----------------
__global__ void k_fin(int layer, const float* __restrict__ gamma,
                      const float* __restrict__ beta) {
    int h = threadIdx.x;  // 128
    float m = g_sum[layer * DH + h] * (1.f / NN);
    float var = g_sq[layer * DH + h] * (1.f / NN) - m * m;
    float rs = rsqrtf(var + BN_EPS);
    float sc = gamma[h] * rs;
    g_scale[layer * DH + h] = sc;
    g_shift[layer * DH + h] = beta[h] - m * sc;
}

// ---------------- pooling ----------------
__global__ void k_count(const int* __restrict__ bidx) {
    int i = blockIdx.x * blockDim.x + threadIdx.x;
    if (i < NN) atomicAdd(&g_cnt[bidx[i]], 1);
}

// segmented pooling: warp owns 8 contiguous nodes; batch_idx is sorted, so
// accumulate in registers and flush atomics only on graph-id change.
__global__ void __launch_bounds__(256) k_pool(const int* __restrict__ bidx,
                                              float* __restrict__ out) {
    int tid = threadIdx.x;
    int warp = (blockIdx.x * 8 + (tid >> 5));
    int base = warp * 8;
    if (base >= NN) return;
    int lane = tid & 31;
    int f = lane * 4;
    const int L2 = (NL - 1) * DH;
    float s0 = g_scale[L2 + f], s1 = g_scale[L2 + f + 1],
          s2 = g_scale[L2 + f + 2], s3 = g_scale[L2 + f + 3];
    float t0 = g_shift[L2 + f], t1 = g_shift[L2 + f + 1],
          t2 = g_shift[L2 + f + 2], t3 = g_shift[L2 + f + 3];

    float a0 = 0.f, a1 = 0.f, a2 = 0.f, a3 = 0.f;
    int cur = bidx[base];
    int end = base + 8 < NN ? base + 8 : NN;
    for (int n = base; n < end; ++n) {
        int gi = bidx[n];
        if (gi != cur) {
            float* o = out + (size_t)cur * DH + f;
            atomicAdd(o + 0, a0); atomicAdd(o + 1, a1);
            atomicAdd(o + 2, a2); atomicAdd(o + 3, a3);
            a0 = a1 = a2 = a3 = 0.f;
            cur = gi;
        }
        float4 h = *(const float4*)(g_hag + (size_t)n * DH + f);
        a0 += elu1(fmaf(h.x, s0, t0));
        a1 += elu1(fmaf(h.y, s1, t1));
        a2 += elu1(fmaf(h.z, s2, t2));
        a3 += elu1(fmaf(h.w, s3, t3));
    }
    float* o = out + (size_t)cur * DH + f;
    atomicAdd(o + 0, a0); atomicAdd(o + 1, a1);
    atomicAdd(o + 2, a2); atomicAdd(o + 3, a3);
}

__global__ void k_div(float* __restrict__ out) {
    int i = blockIdx.x * blockDim.x + threadIdx.x;
    if (i < NG * DH) {
        float c = (float)g_cnt[i >> 7];
        out[i] = out[i] / fmaxf(c, 1.f);
    }
}

// ---------------- launch ----------------
extern "C" void kernel_launch(void* const* d_in, const int* in_sizes, int n_in,
                              void* d_out, int out_size) {
    const float* x      = (const float*)d_in[0];
    const float* Ws     = (const float*)d_in[1];
    const float* bs     = (const float*)d_in[2];
    const float* gammas = (const float*)d_in[3];
    const float* betas  = (const float*)d_in[4];
    const int*   ei     = (const int*)d_in[5];
    const int*   bidx   = (const int*)d_in[6];
    float*       out    = (float*)d_out;

    const int* src = ei;
    const int* dst = ei + NE;

    k_init<<<(NN + 255) / 256, 256>>>();
    k_deg<<<(NE + 255) / 256, 256>>>(dst);
    k_bsum<<<SCAN_NB, SCAN_T>>>();
    k_bscan<<<1, 256>>>();
    k_lscan<<<SCAN_NB, SCAN_T>>>();
    k_fill<<<(NE + 255) / 256, 256>>>(src, dst);

    int gemm_grid = (NN + 127) / 128;
    int agg_grid = (NN + 7) / 8;
    for (int l = 0; l < NL; ++l) {
        k_gemm<<<gemm_grid, 256>>>(l, x, Ws + (size_t)l * DH * DH);
        k_agg<<<agg_grid, 256>>>(l, bs + l * DH);
        k_fin<<<1, DH>>>(l, gammas + l * DH, betas + l * DH);
    }

    cudaMemsetAsync(d_out, 0, (size_t)NG * DH * sizeof(float));
    k_count<<<(NN + 255) / 256, 256>>>(bidx);
    int pool_grid = (NN + 63) / 64;   // 8 warps/block * 8 nodes/warp
    k_pool<<<pool_grid, 256>>>(bidx, out);
    k_div<<<(NG * DH + 255) / 256, 256>>>(out);
}

// round 4
// speedup vs baseline: 1.6586x; 1.3643x over previous
#include <cuda_runtime.h>
#include <cuda_bf16.h>
#include <math.h>
#include <stdint.h>

#define NN 50000
#define NE 640000
#define DH 128
#define NG 1024
#define NL 3
#define BN_EPS 1e-5f

#define SCAN_T 256
#define SCAN_NB ((NN + SCAN_T - 1) / SCAN_T)   // 196

__device__ __forceinline__ uint32_t smem_to_u32(const void* p) {
    uint32_t a;
    asm("{ .reg .u64 t; cvta.to.shared.u64 t, %1; cvt.u32.u64 %0, t; }" : "=r"(a) : "l"(p));
    return a;
}

// ---------------- scratch ----------------
__device__ int   g_deg[NN];
__device__ int   g_off[NN + 1];
__device__ int   g_cur[NN];
__device__ float g_dinv[NN];
__device__ int   g_csr[NE];
__device__ int   g_bsum[SCAN_NB];
__device__ int   g_boff[SCAN_NB];
__device__ float g_gbuf[(size_t)NN * DH];
__device__ float g_hag[(size_t)NN * DH];
__device__ float g_sum[NL * DH];
__device__ float g_sq[NL * DH];
__device__ float g_scale[NL * DH];
__device__ float g_shift[NL * DH];
__device__ int   g_cnt[NG];
// W^T as bf16 hi/lo, per layer 128x128 bf16 = 32KB, XOR-swizzled block layout
__device__ unsigned short g_whi[NL * 16384];
__device__ unsigned short g_wlo[NL * 16384];

__device__ __forceinline__ float elu1(float v) {
    return v > 0.f ? v : (expf(v) - 1.f);
}

// ---------------- preprocessing ----------------
__global__ void k_init() {
    int i = blockIdx.x * blockDim.x + threadIdx.x;
    if (i < NN) g_deg[i] = 0;
    if (i < NL * DH) { g_sum[i] = 0.f; g_sq[i] = 0.f; }
    if (i < NG) g_cnt[i] = 0;
}

__global__ void k_deg(const int* __restrict__ dst) {
    int e = blockIdx.x * blockDim.x + threadIdx.x;
    if (e < NE) atomicAdd(&g_deg[dst[e]], 1);
}

__global__ void __launch_bounds__(SCAN_T) k_bsum() {
    int i = blockIdx.x * SCAN_T + threadIdx.x;
    int v = (i < NN) ? g_deg[i] : 0;
    #pragma unroll
    for (int o = 16; o; o >>= 1) v += __shfl_down_sync(0xffffffffu, v, o);
    __shared__ int ws[SCAN_T / 32];
    if ((threadIdx.x & 31) == 0) ws[threadIdx.x >> 5] = v;
    __syncthreads();
    if (threadIdx.x < SCAN_T / 32) {
        int s = ws[threadIdx.x];
        #pragma unroll
        for (int o = SCAN_T / 64; o; o >>= 1) s += __shfl_down_sync(0xffu, s, o);
        if (threadIdx.x == 0) g_bsum[blockIdx.x] = s;
    }
}

__global__ void __launch_bounds__(256) k_bscan() {
    int tid = threadIdx.x;
    int lane = tid & 31, wid = tid >> 5;
    int v = (tid < SCAN_NB) ? g_bsum[tid] : 0;
    int incl = v;
    #pragma unroll
    for (int o = 1; o < 32; o <<= 1) {
        int t = __shfl_up_sync(0xffffffffu, incl, o);
        if (lane >= o) incl += t;
    }
    __shared__ int wtot[8];
    if (lane == 31) wtot[wid] = incl;
    __syncthreads();
    if (tid < 8) {
        int s = wtot[tid];
        int si = s;
        #pragma unroll
        for (int o = 1; o < 8; o <<= 1) {
            int t = __shfl_up_sync(0xffu, si, o);
            if (tid >= o) si += t;
        }
        wtot[tid] = si - s;
    }
    __syncthreads();
    incl += wtot[wid];
    if (tid < SCAN_NB) g_boff[tid] = incl - v;
    if (tid == 255) g_off[NN] = incl;
}

__global__ void __launch_bounds__(SCAN_T) k_lscan() {
    int tid = threadIdx.x;
    int lane = tid & 31, wid = tid >> 5;
    int i = blockIdx.x * SCAN_T + tid;
    int v = (i < NN) ? g_deg[i] : 0;
    int incl = v;
    #pragma unroll
    for (int o = 1; o < 32; o <<= 1) {
        int t = __shfl_up_sync(0xffffffffu, incl, o);
        if (lane >= o) incl += t;
    }
    __shared__ int wtot[SCAN_T / 32];
    if (lane == 31) wtot[wid] = incl;
    __syncthreads();
    if (tid < SCAN_T / 32) {
        int s = wtot[tid];
        int si = s;
        #pragma unroll
        for (int o = 1; o < SCAN_T / 32; o <<= 1) {
            int t = __shfl_up_sync(0xffu, si, o);
            if (tid >= o) si += t;
        }
        wtot[tid] = si - s;
    }
    __syncthreads();
    int excl = incl - v + wtot[wid] + g_boff[blockIdx.x];
    if (i < NN) {
        g_off[i] = excl;
        g_cur[i] = excl;
        g_dinv[i] = rsqrtf((float)(v + 1));
    }
}

__global__ void k_fill(const int* __restrict__ src, const int* __restrict__ dst) {
    int e = blockIdx.x * blockDim.x + threadIdx.x;
    if (e < NE) {
        int d = dst[e];
        int pos = atomicAdd(&g_cur[d], 1);
        g_csr[pos] = src[e];
    }
}

// swizzled byte offset within a 128x128-bf16 (32KB) tile:
// row r (0..127), k element (0..127). 16B chunk index c = k/8, swizzle c^(r&7).
__device__ __forceinline__ int swz_off(int r, int kchunk) {
    return r * 256 + ((kchunk ^ (r & 7)) << 4);
}

// ---------------- W convert: Ws[l][k][n] -> W^T[n][k] bf16 hi/lo, swizzled
__global__ void k_wconv(const float* __restrict__ Ws) {
    int idx = blockIdx.x * 256 + threadIdx.x;   // NL*16384
    int l = idx >> 14;
    int rem = idx & 16383;
    int n = rem & 127;
    int k = rem >> 7;
    float w = Ws[(size_t)l * 16384 + k * 128 + n];
    __nv_bfloat16 hi = __float2bfloat16(w);
    float lof = w - __bfloat162float(hi);
    __nv_bfloat16 lo = __float2bfloat16(lof);
    int off = swz_off(n, k >> 3) + (k & 7) * 2;
    int a = l * 16384 + (off >> 1);
    g_whi[a] = __bfloat16_as_ushort(hi);
    g_wlo[a] = __bfloat16_as_ushort(lo);
}

// ---------------- HMMA GEMM: g = dinv * (A' @ W) ----------------
// 128x128x128 block, 8 warps, warp tile 32x64, bf16 3-way split
#define SA_HI 0
#define SA_LO 32768
#define SB_HI 65536
#define SB_LO 98304
#define SM_TOTAL 131072

__device__ __forceinline__ void ldsm4(uint32_t& r0, uint32_t& r1, uint32_t& r2,
                                      uint32_t& r3, uint32_t addr) {
    asm volatile("ldmatrix.sync.aligned.m8n8.x4.shared.b16 {%0,%1,%2,%3}, [%4];"
                 : "=r"(r0), "=r"(r1), "=r"(r2), "=r"(r3) : "r"(addr));
}
__device__ __forceinline__ void mma16816(float* d, const uint32_t* a, const uint32_t* b) {
    asm volatile(
        "mma.sync.aligned.m16n8k16.row.col.f32.bf16.bf16.f32 "
        "{%0,%1,%2,%3}, {%4,%5,%6,%7}, {%8,%9}, {%0,%1,%2,%3};"
        : "+f"(d[0]), "+f"(d[1]), "+f"(d[2]), "+f"(d[3])
        : "r"(a[0]), "r"(a[1]), "r"(a[2]), "r"(a[3]), "r"(b[0]), "r"(b[1]));
}

__global__ void __launch_bounds__(256) k_gemm_tc(int layer, const float* __restrict__ x) {
    extern __shared__ char sm[];
    uint32_t sm_u = smem_to_u32(sm);
    int tid = threadIdx.x;
    int wid = tid >> 5, lane = tid & 31;

    // --- load pre-swizzled W tiles (linear 32KB copies preserve layout)
    {
        const int4* whi = (const int4*)(g_whi + layer * 16384);
        const int4* wlo = (const int4*)(g_wlo + layer * 16384);
        int4* bh = (int4*)(sm + SB_HI);
        int4* bl = (int4*)(sm + SB_LO);
        #pragma unroll
        for (int i = 0; i < 8; ++i) {
            bh[tid + i * 256] = whi[tid + i * 256];
            bl[tid + i * 256] = wlo[tid + i * 256];
        }
    }

    // --- convert A' rows (fused BN+ELU for layer>0) into swizzled bf16 hi/lo
    {
        const float* A = (layer == 0) ? x : g_hag;
        const float* sc = g_scale + (layer > 0 ? (layer - 1) * DH : 0);
        const float* sh = g_shift + (layer > 0 ? (layer - 1) * DH : 0);
        int row = tid >> 1, half = tid & 1;
        int gr = blockIdx.x * 128 + row;
        if (gr < NN) {
            const float4* ap = (const float4*)(A + (size_t)gr * DH + half * 64);
            #pragma unroll
            for (int c8 = 0; c8 < 8; ++c8) {
                int kc = half * 8 + c8;       // global 16B chunk (8 bf16)
                float4 v0 = ap[c8 * 2];
                float4 v1 = ap[c8 * 2 + 1];
                float f[8] = {v0.x, v0.y, v0.z, v0.w, v1.x, v1.y, v1.z, v1.w};
                if (layer > 0) {
                    int k0 = kc * 8;
                    #pragma unroll
                    for (int c = 0; c < 8; ++c)
                        f[c] = elu1(fmaf(f[c], sc[k0 + c], sh[k0 + c]));
                }
                uint32_t hp[4], lp[4];
                #pragma unroll
                for (int p = 0; p < 4; ++p) {
                    __nv_bfloat16 h0 = __float2bfloat16(f[p * 2]);
                    __nv_bfloat16 h1 = __float2bfloat16(f[p * 2 + 1]);
                    __nv_bfloat16 l0 = __float2bfloat16(f[p * 2] - __bfloat162float(h0));
                    __nv_bfloat16 l1 = __float2bfloat16(f[p * 2 + 1] - __bfloat162float(h1));
                    hp[p] = (uint32_t)__bfloat16_as_ushort(h0) |
                            ((uint32_t)__bfloat16_as_ushort(h1) << 16);
                    lp[p] = (uint32_t)__bfloat16_as_ushort(l0) |
                            ((uint32_t)__bfloat16_as_ushort(l1) << 16);
                }
                int off = swz_off(row, kc);
                *(int4*)(sm + SA_HI + off) = make_int4(hp[0], hp[1], hp[2], hp[3]);
                *(int4*)(sm + SA_LO + off) = make_int4(lp[0], lp[1], lp[2], lp[3]);
            }
        } else {
            int4 z = make_int4(0, 0, 0, 0);
            #pragma unroll
            for (int c8 = 0; c8 < 8; ++c8) {
                int off = swz_off(row, half * 8 + c8);
                *(int4*)(sm + SA_HI + off) = z;
                *(int4*)(sm + SA_LO + off) = z;
            }
        }
    }
    __syncthreads();

    // --- warp tiles: warp_m in {0..3} rows, warp_n in {0,1} cols
    int warp_m = (wid & 3) * 32;
    int warp_n = (wid >> 2) * 64;

    float acc[2][8][4];
    #pragma unroll
    for (int i = 0; i < 2; ++i)
        #pragma unroll
        for (int j = 0; j < 8; ++j)
            #pragma unroll
            for (int c = 0; c < 4; ++c) acc[i][j][c] = 0.f;

    // ldmatrix lane-address components
    int sub = lane >> 3, l7 = lane & 7;
    // A: rows for mf: warp_m + mf*16 + (sub&1)*8 + l7 ; kchunk = ks*2 + (sub>>1)
    int a_r0 = warp_m + (sub & 1) * 8 + l7;
    int a_cadd = sub >> 1;
    // B (x4 covers nf pair): row = warp_n + (p*2 + (sub>>1))*8 + l7 ; kchunk = ks*2 + (sub&1)
    int b_nsel = (sub >> 1) * 8 + l7;
    int b_cadd = sub & 1;

    #pragma unroll
    for (int pass = 0; pass < 3; ++pass) {
        uint32_t aBase = sm_u + ((pass == 2) ? SA_LO : SA_HI);
        uint32_t bBase = sm_u + ((pass == 1) ? SB_LO : SB_HI);
        #pragma unroll
        for (int ks = 0; ks < 8; ++ks) {
            uint32_t a[2][4];
            #pragma unroll
            for (int mf = 0; mf < 2; ++mf) {
                int r = a_r0 + mf * 16;
                int kc = ks * 2 + a_cadd;
                ldsm4(a[mf][0], a[mf][1], a[mf][2], a[mf][3],
                      aBase + swz_off(r, kc));
            }
            uint32_t b[8][2];
            #pragma unroll
            for (int p = 0; p < 4; ++p) {
                int r = warp_n + p * 16 + b_nsel;
                int kc = ks * 2 + b_cadd;
                ldsm4(b[p * 2][0], b[p * 2][1], b[p * 2 + 1][0], b[p * 2 + 1][1],
                      bBase + swz_off(r, kc));
            }
            #pragma unroll
            for (int mf = 0; mf < 2; ++mf)
                #pragma unroll
                for (int nf = 0; nf < 8; ++nf)
                    mma16816(acc[mf][nf], a[mf], b[nf]);
        }
    }

    // --- epilogue: scale rows by dinv, store to g_gbuf
    int qr = lane >> 2, qc = (lane & 3) * 2;
    #pragma unroll
    for (int mf = 0; mf < 2; ++mf) {
        int r0 = blockIdx.x * 128 + warp_m + mf * 16 + qr;
        int r1 = r0 + 8;
        float d0 = (r0 < NN) ? g_dinv[r0] : 0.f;
        float d1 = (r1 < NN) ? g_dinv[r1] : 0.f;
        #pragma unroll
        for (int nf = 0; nf < 8; ++nf) {
            int col = warp_n + nf * 8 + qc;
            if (r0 < NN) {
                float2 o = make_float2(acc[mf][nf][0] * d0, acc[mf][nf][1] * d0);
                *(float2*)(g_gbuf + (size_t)r0 * DH + col) = o;
            }
            if (r1 < NN) {
                float2 o = make_float2(acc[mf][nf][2] * d1, acc[mf][nf][3] * d1);
                *(float2*)(g_gbuf + (size_t)r1 * DH + col) = o;
            }
        }
    }
}

// ---------------- aggregation ----------------
__global__ void __launch_bounds__(256) k_agg(int layer, const float* __restrict__ bias) {
    __shared__ float s_sum[DH];
    __shared__ float s_sq[DH];
    int tid = threadIdx.x;
    if (tid < DH) { s_sum[tid] = 0.f; s_sq[tid] = 0.f; }
    __syncthreads();

    int node = blockIdx.x * 8 + (tid >> 5);
    int lane = tid & 31;
    if (node < NN) {
        float4 a0 = *(const float4*)(g_gbuf + (size_t)node * DH + lane * 4);
        float4 a1 = make_float4(0.f, 0.f, 0.f, 0.f);
        int s = g_off[node], e2 = g_off[node + 1];
        int p = s;
        for (; p + 1 < e2; p += 2) {
            int s0 = g_csr[p];
            int s1 = g_csr[p + 1];
            float4 v0 = *(const float4*)(g_gbuf + (size_t)s0 * DH + lane * 4);
            float4 v1 = *(const float4*)(g_gbuf + (size_t)s1 * DH + lane * 4);
            a0.x += v0.x; a0.y += v0.y; a0.z += v0.z; a0.w += v0.w;
            a1.x += v1.x; a1.y += v1.y; a1.z += v1.z; a1.w += v1.w;
        }
        if (p < e2) {
            int s0 = g_csr[p];
            float4 v0 = *(const float4*)(g_gbuf + (size_t)s0 * DH + lane * 4);
            a0.x += v0.x; a0.y += v0.y; a0.z += v0.z; a0.w += v0.w;
        }
        float di = g_dinv[node];
        float4 b = ((const float4*)bias)[lane];
        float4 h;
        h.x = fmaf(di, a0.x + a1.x, b.x);
        h.y = fmaf(di, a0.y + a1.y, b.y);
        h.z = fmaf(di, a0.z + a1.z, b.z);
        h.w = fmaf(di, a0.w + a1.w, b.w);
        *(float4*)(g_hag + (size_t)node * DH + lane * 4) = h;

        int f = lane * 4;
        atomicAdd(&s_sum[f + 0], h.x); atomicAdd(&s_sq[f + 0], h.x * h.x);
        atomicAdd(&s_sum[f + 1], h.y); atomicAdd(&s_sq[f + 1], h.y * h.y);
        atomicAdd(&s_sum[f + 2], h.z); atomicAdd(&s_sq[f + 2], h.z * h.z);
        atomicAdd(&s_sum[f + 3], h.w); atomicAdd(&s_sq[f + 3], h.w * h.w);
    }
    __syncthreads();
    if (tid < DH) {
        atomicAdd(&g_sum[layer * DH + tid], s_sum[tid]);
        atomicAdd(&g_sq[layer * DH + tid], s_sq[tid]);
    }
}

// ---------------- BN finalize ----------------
__global__ void k_fin(int layer, const float* __restrict__ gamma,
                      const float* __restrict__ beta) {
    int h = threadIdx.x;
    float m = g_sum[layer * DH + h] * (1.f / NN);
    float var = g_sq[layer * DH + h] * (1.f / NN) - m * m;
    float rs = rsqrtf(var + BN_EPS);
    float sc = gamma[h] * rs;
    g_scale[layer * DH + h] = sc;
    g_shift[layer * DH + h] = beta[h] - m * sc;
}

// ---------------- pooling ----------------
__global__ void k_count(const int* __restrict__ bidx) {
    int i = blockIdx.x * blockDim.x + threadIdx.x;
    if (i < NN) atomicAdd(&g_cnt[bidx[i]], 1);
}

__global__ void __launch_bounds__(256) k_pool(const int* __restrict__ bidx,
                                              float* __restrict__ out) {
    int tid = threadIdx.x;
    int warp = (blockIdx.x * 8 + (tid >> 5));
    int base = warp * 8;
    if (base >= NN) return;
    int lane = tid & 31;
    int f = lane * 4;
    const int L2 = (NL - 1) * DH;
    float s0 = g_scale[L2 + f], s1 = g_scale[L2 + f + 1],
          s2 = g_scale[L2 + f + 2], s3 = g_scale[L2 + f + 3];
    float t0 = g_shift[L2 + f], t1 = g_shift[L2 + f + 1],
          t2 = g_shift[L2 + f + 2], t3 = g_shift[L2 + f + 3];

    float a0 = 0.f, a1 = 0.f, a2 = 0.f, a3 = 0.f;
    int cur = bidx[base];
    int end = base + 8 < NN ? base + 8 : NN;
    for (int n = base; n < end; ++n) {
        int gi = bidx[n];
        if (gi != cur) {
            float* o = out + (size_t)cur * DH + f;
            atomicAdd(o + 0, a0); atomicAdd(o + 1, a1);
            atomicAdd(o + 2, a2); atomicAdd(o + 3, a3);
            a0 = a1 = a2 = a3 = 0.f;
            cur = gi;
        }
        float4 h = *(const float4*)(g_hag + (size_t)n * DH + f);
        a0 += elu1(fmaf(h.x, s0, t0));
        a1 += elu1(fmaf(h.y, s1, t1));
        a2 += elu1(fmaf(h.z, s2, t2));
        a3 += elu1(fmaf(h.w, s3, t3));
    }
    float* o = out + (size_t)cur * DH + f;
    atomicAdd(o + 0, a0); atomicAdd(o + 1, a1);
    atomicAdd(o + 2, a2); atomicAdd(o + 3, a3);
}

__global__ void k_div(float* __restrict__ out) {
    int i = blockIdx.x * blockDim.x + threadIdx.x;
    if (i < NG * DH) {
        float c = (float)g_cnt[i >> 7];
        out[i] = out[i] / fmaxf(c, 1.f);
    }
}

// ---------------- launch ----------------
extern "C" void kernel_launch(void* const* d_in, const int* in_sizes, int n_in,
                              void* d_out, int out_size) {
    const float* x      = (const float*)d_in[0];
    const float* Ws     = (const float*)d_in[1];
    const float* bs     = (const float*)d_in[2];
    const float* gammas = (const float*)d_in[3];
    const float* betas  = (const float*)d_in[4];
    const int*   ei     = (const int*)d_in[5];
    const int*   bidx   = (const int*)d_in[6];
    float*       out    = (float*)d_out;

    const int* src = ei;
    const int* dst = ei + NE;

    cudaFuncSetAttribute(k_gemm_tc, cudaFuncAttributeMaxDynamicSharedMemorySize, SM_TOTAL);

    k_init<<<(NN + 255) / 256, 256>>>();
    k_deg<<<(NE + 255) / 256, 256>>>(dst);
    k_bsum<<<SCAN_NB, SCAN_T>>>();
    k_bscan<<<1, 256>>>();
    k_lscan<<<SCAN_NB, SCAN_T>>>();
    k_fill<<<(NE + 255) / 256, 256>>>(src, dst);
    k_wconv<<<NL * 16384 / 256, 256>>>(Ws);

    int gemm_grid = (NN + 127) / 128;
    int agg_grid = (NN + 7) / 8;
    for (int l = 0; l < NL; ++l) {
        k_gemm_tc<<<gemm_grid, 256, SM_TOTAL>>>(l, x);
        k_agg<<<agg_grid, 256>>>(l, bs + l * DH);
        k_fin<<<1, DH>>>(l, gammas + l * DH, betas + l * DH);
    }

    cudaMemsetAsync(d_out, 0, (size_t)NG * DH * sizeof(float));
    k_count<<<(NN + 255) / 256, 256>>>(bidx);
    int pool_grid = (NN + 63) / 64;
    k_pool<<<pool_grid, 256>>>(bidx, out);
    k_div<<<(NG * DH + 255) / 256, 256>>>(out);
}

// round 5
// speedup vs baseline: 1.7810x; 1.0738x over previous
#include <cuda_runtime.h>
#include <cuda_bf16.h>
#include <math.h>
#include <stdint.h>

#define NN 50000
#define NE 640000
#define DH 128
#define NG 1024
#define NL 3
#define BN_EPS 1e-5f

#define SCAN_T 256
#define SCAN_NB ((NN + SCAN_T - 1) / SCAN_T)   // 196

__device__ __forceinline__ uint32_t smem_to_u32(const void* p) {
    uint32_t a;
    asm("{ .reg .u64 t; cvta.to.shared.u64 t, %1; cvt.u32.u64 %0, t; }" : "=r"(a) : "l"(p));
    return a;
}

// ---------------- scratch ----------------
__device__ int   g_deg[NN];
__device__ int   g_off[NN + 1];
__device__ int   g_cur[NN];
__device__ float g_dinv[NN];
__device__ int   g_csr[NE];
__device__ int   g_bsum[SCAN_NB];
__device__ int   g_boff[SCAN_NB];
__device__ float g_gbuf[(size_t)NN * DH];
__device__ float g_hag[(size_t)NN * DH];
__device__ float g_sum[NL * DH];
__device__ float g_sq[NL * DH];
__device__ float g_scale[NL * DH];
__device__ float g_shift[NL * DH];
__device__ int   g_cnt[NG];
// W^T as bf16 hi/lo, per layer 128x128 bf16 = 32KB, XOR-swizzled block layout
__device__ unsigned short g_whi[NL * 16384];
__device__ unsigned short g_wlo[NL * 16384];

__device__ __forceinline__ float elu1(float v) {
    return v > 0.f ? v : (expf(v) - 1.f);
}

// swizzled byte offset within a 128x128-bf16 (32KB) tile:
__device__ __forceinline__ int swz_off(int r, int kchunk) {
    return r * 256 + ((kchunk ^ (r & 7)) << 4);
}

// ---------------- launch 1: init everything + W convert ----------------
__global__ void k_init_all(const float* __restrict__ Ws) {
    int i = blockIdx.x * 256 + threadIdx.x;   // grid covers 50176
    if (i < NN) g_deg[i] = 0;
    if (i < NL * DH) { g_sum[i] = 0.f; g_sq[i] = 0.f; }
    if (i < NG) g_cnt[i] = 0;
    if (i < NL * 16384) {
        int l = i >> 14;
        int rem = i & 16383;
        int n = rem & 127;
        int k = rem >> 7;
        float w = Ws[(size_t)l * 16384 + k * 128 + n];
        __nv_bfloat16 hi = __float2bfloat16(w);
        float lof = w - __bfloat162float(hi);
        __nv_bfloat16 lo = __float2bfloat16(lof);
        int off = swz_off(n, k >> 3) + (k & 7) * 2;
        int a = l * 16384 + (off >> 1);
        g_whi[a] = __bfloat16_as_ushort(hi);
        g_wlo[a] = __bfloat16_as_ushort(lo);
    }
}

// ---------------- launch 2: degree histogram + graph counts ----------------
__global__ void k_deg(const int* __restrict__ dst, const int* __restrict__ bidx) {
    int e = blockIdx.x * blockDim.x + threadIdx.x;
    if (e < NE) atomicAdd(&g_deg[dst[e]], 1);
    if (e < NN) atomicAdd(&g_cnt[bidx[e]], 1);
}

// ---------------- launch 3: dinv ----------------
__global__ void k_dinv() {
    int i = blockIdx.x * blockDim.x + threadIdx.x;
    if (i < NN) g_dinv[i] = rsqrtf((float)(g_deg[i] + 1));
}

// ---------------- scans ----------------
__global__ void __launch_bounds__(SCAN_T) k_bsum() {
    int i = blockIdx.x * SCAN_T + threadIdx.x;
    int v = (i < NN) ? g_deg[i] : 0;
    #pragma unroll
    for (int o = 16; o; o >>= 1) v += __shfl_down_sync(0xffffffffu, v, o);
    __shared__ int ws[SCAN_T / 32];
    if ((threadIdx.x & 31) == 0) ws[threadIdx.x >> 5] = v;
    __syncthreads();
    if (threadIdx.x < SCAN_T / 32) {
        int s = ws[threadIdx.x];
        #pragma unroll
        for (int o = SCAN_T / 64; o; o >>= 1) s += __shfl_down_sync(0xffu, s, o);
        if (threadIdx.x == 0) g_bsum[blockIdx.x] = s;
    }
}

__global__ void __launch_bounds__(256) k_bscan() {
    int tid = threadIdx.x;
    int lane = tid & 31, wid = tid >> 5;
    int v = (tid < SCAN_NB) ? g_bsum[tid] : 0;
    int incl = v;
    #pragma unroll
    for (int o = 1; o < 32; o <<= 1) {
        int t = __shfl_up_sync(0xffffffffu, incl, o);
        if (lane >= o) incl += t;
    }
    __shared__ int wtot[8];
    if (lane == 31) wtot[wid] = incl;
    __syncthreads();
    if (tid < 8) {
        int s = wtot[tid];
        int si = s;
        #pragma unroll
        for (int o = 1; o < 8; o <<= 1) {
            int t = __shfl_up_sync(0xffu, si, o);
            if (tid >= o) si += t;
        }
        wtot[tid] = si - s;
    }
    __syncthreads();
    incl += wtot[wid];
    if (tid < SCAN_NB) g_boff[tid] = incl - v;
    if (tid == 255) g_off[NN] = incl;
}

__global__ void __launch_bounds__(SCAN_T) k_lscan() {
    int tid = threadIdx.x;
    int lane = tid & 31, wid = tid >> 5;
    int i = blockIdx.x * SCAN_T + tid;
    int v = (i < NN) ? g_deg[i] : 0;
    int incl = v;
    #pragma unroll
    for (int o = 1; o < 32; o <<= 1) {
        int t = __shfl_up_sync(0xffffffffu, incl, o);
        if (lane >= o) incl += t;
    }
    __shared__ int wtot[SCAN_T / 32];
    if (lane == 31) wtot[wid] = incl;
    __syncthreads();
    if (tid < SCAN_T / 32) {
        int s = wtot[tid];
        int si = s;
        #pragma unroll
        for (int o = 1; o < SCAN_T / 32; o <<= 1) {
            int t = __shfl_up_sync(0xffu, si, o);
            if (tid >= o) si += t;
        }
        wtot[tid] = si - s;
    }
    __syncthreads();
    int excl = incl - v + wtot[wid] + g_boff[blockIdx.x];
    if (i < NN) {
        g_off[i] = excl;
        g_cur[i] = excl;
    }
}

__global__ void k_fill(const int* __restrict__ src, const int* __restrict__ dst) {
    int e = blockIdx.x * blockDim.x + threadIdx.x;
    if (e < NE) {
        int d = dst[e];
        int pos = atomicAdd(&g_cur[d], 1);
        g_csr[pos] = src[e];
    }
}

// ---------------- HMMA GEMM: g = dinv * (A' @ W) ----------------
#define SA_HI 0
#define SA_LO 32768
#define SB_HI 65536
#define SB_LO 98304
#define SM_TOTAL 131072

__device__ __forceinline__ void ldsm4(uint32_t& r0, uint32_t& r1, uint32_t& r2,
                                      uint32_t& r3, uint32_t addr) {
    asm volatile("ldmatrix.sync.aligned.m8n8.x4.shared.b16 {%0,%1,%2,%3}, [%4];"
                 : "=r"(r0), "=r"(r1), "=r"(r2), "=r"(r3) : "r"(addr));
}
__device__ __forceinline__ void mma16816(float* d, const uint32_t* a, const uint32_t* b) {
    asm volatile(
        "mma.sync.aligned.m16n8k16.row.col.f32.bf16.bf16.f32 "
        "{%0,%1,%2,%3}, {%4,%5,%6,%7}, {%8,%9}, {%0,%1,%2,%3};"
        : "+f"(d[0]), "+f"(d[1]), "+f"(d[2]), "+f"(d[3])
        : "r"(a[0]), "r"(a[1]), "r"(a[2]), "r"(a[3]), "r"(b[0]), "r"(b[1]));
}

__global__ void __launch_bounds__(256) k_gemm_tc(int layer, const float* __restrict__ x) {
    extern __shared__ char sm[];
    uint32_t sm_u = smem_to_u32(sm);
    int tid = threadIdx.x;
    int wid = tid >> 5, lane = tid & 31;

    // load pre-swizzled W tiles
    {
        const int4* whi = (const int4*)(g_whi + layer * 16384);
        const int4* wlo = (const int4*)(g_wlo + layer * 16384);
        int4* bh = (int4*)(sm + SB_HI);
        int4* bl = (int4*)(sm + SB_LO);
        #pragma unroll
        for (int i = 0; i < 8; ++i) {
            bh[tid + i * 256] = whi[tid + i * 256];
            bl[tid + i * 256] = wlo[tid + i * 256];
        }
    }

    // convert A' rows (fused BN+ELU for layer>0) into swizzled bf16 hi/lo
    {
        const float* A = (layer == 0) ? x : g_hag;
        const float* sc = g_scale + (layer > 0 ? (layer - 1) * DH : 0);
        const float* sh = g_shift + (layer > 0 ? (layer - 1) * DH : 0);
        int row = tid >> 1, half = tid & 1;
        int gr = blockIdx.x * 128 + row;
        if (gr < NN) {
            const float4* ap = (const float4*)(A + (size_t)gr * DH + half * 64);
            #pragma unroll
            for (int c8 = 0; c8 < 8; ++c8) {
                int kc = half * 8 + c8;
                float4 v0 = ap[c8 * 2];
                float4 v1 = ap[c8 * 2 + 1];
                float f[8] = {v0.x, v0.y, v0.z, v0.w, v1.x, v1.y, v1.z, v1.w};
                if (layer > 0) {
                    int k0 = kc * 8;
                    #pragma unroll
                    for (int c = 0; c < 8; ++c)
                        f[c] = elu1(fmaf(f[c], sc[k0 + c], sh[k0 + c]));
                }
                uint32_t hp[4], lp[4];
                #pragma unroll
                for (int p = 0; p < 4; ++p) {
                    __nv_bfloat16 h0 = __float2bfloat16(f[p * 2]);
                    __nv_bfloat16 h1 = __float2bfloat16(f[p * 2 + 1]);
                    __nv_bfloat16 l0 = __float2bfloat16(f[p * 2] - __bfloat162float(h0));
                    __nv_bfloat16 l1 = __float2bfloat16(f[p * 2 + 1] - __bfloat162float(h1));
                    hp[p] = (uint32_t)__bfloat16_as_ushort(h0) |
                            ((uint32_t)__bfloat16_as_ushort(h1) << 16);
                    lp[p] = (uint32_t)__bfloat16_as_ushort(l0) |
                            ((uint32_t)__bfloat16_as_ushort(l1) << 16);
                }
                int off = swz_off(row, kc);
                *(int4*)(sm + SA_HI + off) = make_int4(hp[0], hp[1], hp[2], hp[3]);
                *(int4*)(sm + SA_LO + off) = make_int4(lp[0], lp[1], lp[2], lp[3]);
            }
        } else {
            int4 z = make_int4(0, 0, 0, 0);
            #pragma unroll
            for (int c8 = 0; c8 < 8; ++c8) {
                int off = swz_off(row, half * 8 + c8);
                *(int4*)(sm + SA_HI + off) = z;
                *(int4*)(sm + SA_LO + off) = z;
            }
        }
    }
    __syncthreads();

    int warp_m = (wid & 3) * 32;
    int warp_n = (wid >> 2) * 64;

    float acc[2][8][4];
    #pragma unroll
    for (int i = 0; i < 2; ++i)
        #pragma unroll
        for (int j = 0; j < 8; ++j)
            #pragma unroll
            for (int c = 0; c < 4; ++c) acc[i][j][c] = 0.f;

    int sub = lane >> 3, l7 = lane & 7;
    int a_r0 = warp_m + (sub & 1) * 8 + l7;
    int a_cadd = sub >> 1;
    int b_nsel = (sub >> 1) * 8 + l7;
    int b_cadd = sub & 1;

    #pragma unroll
    for (int pass = 0; pass < 3; ++pass) {
        uint32_t aBase = sm_u + ((pass == 2) ? SA_LO : SA_HI);
        uint32_t bBase = sm_u + ((pass == 1) ? SB_LO : SB_HI);
        #pragma unroll
        for (int ks = 0; ks < 8; ++ks) {
            uint32_t a[2][4];
            #pragma unroll
            for (int mf = 0; mf < 2; ++mf) {
                int r = a_r0 + mf * 16;
                int kc = ks * 2 + a_cadd;
                ldsm4(a[mf][0], a[mf][1], a[mf][2], a[mf][3],
                      aBase + swz_off(r, kc));
            }
            uint32_t b[8][2];
            #pragma unroll
            for (int p = 0; p < 4; ++p) {
                int r = warp_n + p * 16 + b_nsel;
                int kc = ks * 2 + b_cadd;
                ldsm4(b[p * 2][0], b[p * 2][1], b[p * 2 + 1][0], b[p * 2 + 1][1],
                      bBase + swz_off(r, kc));
            }
            #pragma unroll
            for (int mf = 0; mf < 2; ++mf)
                #pragma unroll
                for (int nf = 0; nf < 8; ++nf)
                    mma16816(acc[mf][nf], a[mf], b[nf]);
        }
    }

    int qr = lane >> 2, qc = (lane & 3) * 2;
    #pragma unroll
    for (int mf = 0; mf < 2; ++mf) {
        int r0 = blockIdx.x * 128 + warp_m + mf * 16 + qr;
        int r1 = r0 + 8;
        float d0 = (r0 < NN) ? g_dinv[r0] : 0.f;
        float d1 = (r1 < NN) ? g_dinv[r1] : 0.f;
        #pragma unroll
        for (int nf = 0; nf < 8; ++nf) {
            int col = warp_n + nf * 8 + qc;
            if (r0 < NN) {
                float2 o = make_float2(acc[mf][nf][0] * d0, acc[mf][nf][1] * d0);
                *(float2*)(g_gbuf + (size_t)r0 * DH + col) = o;
            }
            if (r1 < NN) {
                float2 o = make_float2(acc[mf][nf][2] * d1, acc[mf][nf][3] * d1);
                *(float2*)(g_gbuf + (size_t)r1 * DH + col) = o;
            }
        }
    }
}

// ---------------- aggregation: 4 nodes per warp, 32 nodes per block ----------
__global__ void __launch_bounds__(256) k_agg(int layer, const float* __restrict__ bias) {
    __shared__ float s_sum[DH];
    __shared__ float s_sq[DH];
    int tid = threadIdx.x;
    if (tid < DH) { s_sum[tid] = 0.f; s_sq[tid] = 0.f; }
    __syncthreads();

    int warp = tid >> 5, lane = tid & 31;
    int base = blockIdx.x * 32 + warp * 4;
    int f = lane * 4;
    float4 b = ((const float4*)bias)[lane];

    float ls0 = 0.f, ls1 = 0.f, ls2 = 0.f, ls3 = 0.f;
    float lq0 = 0.f, lq1 = 0.f, lq2 = 0.f, lq3 = 0.f;

    int nend = base + 4 < NN ? base + 4 : NN;
    for (int node = base; node < nend; ++node) {
        float4 a0 = *(const float4*)(g_gbuf + (size_t)node * DH + f);
        float4 a1 = make_float4(0.f, 0.f, 0.f, 0.f);
        int s = g_off[node], e2 = g_off[node + 1];
        int p = s;
        for (; p + 1 < e2; p += 2) {
            int s0 = g_csr[p];
            int s1 = g_csr[p + 1];
            float4 v0 = *(const float4*)(g_gbuf + (size_t)s0 * DH + f);
            float4 v1 = *(const float4*)(g_gbuf + (size_t)s1 * DH + f);
            a0.x += v0.x; a0.y += v0.y; a0.z += v0.z; a0.w += v0.w;
            a1.x += v1.x; a1.y += v1.y; a1.z += v1.z; a1.w += v1.w;
        }
        if (p < e2) {
            int s0 = g_csr[p];
            float4 v0 = *(const float4*)(g_gbuf + (size_t)s0 * DH + f);
            a0.x += v0.x; a0.y += v0.y; a0.z += v0.z; a0.w += v0.w;
        }
        float di = g_dinv[node];
        float4 h;
        h.x = fmaf(di, a0.x + a1.x, b.x);
        h.y = fmaf(di, a0.y + a1.y, b.y);
        h.z = fmaf(di, a0.z + a1.z, b.z);
        h.w = fmaf(di, a0.w + a1.w, b.w);
        *(float4*)(g_hag + (size_t)node * DH + f) = h;

        ls0 += h.x; lq0 += h.x * h.x;
        ls1 += h.y; lq1 += h.y * h.y;
        ls2 += h.z; lq2 += h.z * h.z;
        ls3 += h.w; lq3 += h.w * h.w;
    }
    atomicAdd(&s_sum[f + 0], ls0); atomicAdd(&s_sq[f + 0], lq0);
    atomicAdd(&s_sum[f + 1], ls1); atomicAdd(&s_sq[f + 1], lq1);
    atomicAdd(&s_sum[f + 2], ls2); atomicAdd(&s_sq[f + 2], lq2);
    atomicAdd(&s_sum[f + 3], ls3); atomicAdd(&s_sq[f + 3], lq3);
    __syncthreads();
    if (tid < DH) {
        atomicAdd(&g_sum[layer * DH + tid], s_sum[tid]);
        atomicAdd(&g_sq[layer * DH + tid], s_sq[tid]);
    }
}

// ---------------- BN finalize ----------------
__global__ void k_fin(int layer, const float* __restrict__ gamma,
                      const float* __restrict__ beta) {
    int h = threadIdx.x;
    float m = g_sum[layer * DH + h] * (1.f / NN);
    float var = g_sq[layer * DH + h] * (1.f / NN) - m * m;
    float rs = rsqrtf(var + BN_EPS);
    float sc = gamma[h] * rs;
    g_scale[layer * DH + h] = sc;
    g_shift[layer * DH + h] = beta[h] - m * sc;
}

// ---------------- pooling ----------------
__global__ void __launch_bounds__(256) k_pool(const int* __restrict__ bidx,
                                              float* __restrict__ out) {
    int tid = threadIdx.x;
    int warp = (blockIdx.x * 8 + (tid >> 5));
    int base = warp * 8;
    if (base >= NN) return;
    int lane = tid & 31;
    int f = lane * 4;
    const int L2 = (NL - 1) * DH;
    float s0 = g_scale[L2 + f], s1 = g_scale[L2 + f + 1],
          s2 = g_scale[L2 + f + 2], s3 = g_scale[L2 + f + 3];
    float t0 = g_shift[L2 + f], t1 = g_shift[L2 + f + 1],
          t2 = g_shift[L2 + f + 2], t3 = g_shift[L2 + f + 3];

    float a0 = 0.f, a1 = 0.f, a2 = 0.f, a3 = 0.f;
    int cur = bidx[base];
    int end = base + 8 < NN ? base + 8 : NN;
    for (int n = base; n < end; ++n) {
        int gi = bidx[n];
        if (gi != cur) {
            float* o = out + (size_t)cur * DH + f;
            atomicAdd(o + 0, a0); atomicAdd(o + 1, a1);
            atomicAdd(o + 2, a2); atomicAdd(o + 3, a3);
            a0 = a1 = a2 = a3 = 0.f;
            cur = gi;
        }
        float4 h = *(const float4*)(g_hag + (size_t)n * DH + f);
        a0 += elu1(fmaf(h.x, s0, t0));
        a1 += elu1(fmaf(h.y, s1, t1));
        a2 += elu1(fmaf(h.z, s2, t2));
        a3 += elu1(fmaf(h.w, s3, t3));
    }
    float* o = out + (size_t)cur * DH + f;
    atomicAdd(o + 0, a0); atomicAdd(o + 1, a1);
    atomicAdd(o + 2, a2); atomicAdd(o + 3, a3);
}

__global__ void k_div(float* __restrict__ out) {
    int i = blockIdx.x * blockDim.x + threadIdx.x;
    if (i < NG * DH) {
        float c = (float)g_cnt[i >> 7];
        out[i] = out[i] / fmaxf(c, 1.f);
    }
}

// ---------------- launch ----------------
extern "C" void kernel_launch(void* const* d_in, const int* in_sizes, int n_in,
                              void* d_out, int out_size) {
    const float* x      = (const float*)d_in[0];
    const float* Ws     = (const float*)d_in[1];
    const float* bs     = (const float*)d_in[2];
    const float* gammas = (const float*)d_in[3];
    const float* betas  = (const float*)d_in[4];
    const int*   ei     = (const int*)d_in[5];
    const int*   bidx   = (const int*)d_in[6];
    float*       out    = (float*)d_out;

    const int* src = ei;
    const int* dst = ei + NE;

    cudaFuncSetAttribute(k_gemm_tc, cudaFuncAttributeMaxDynamicSharedMemorySize, SM_TOTAL);

    int gemm_grid = (NN + 127) / 128;
    int agg_grid = (NN + 31) / 32;

    k_init_all<<<(NN + 255) / 256, 256>>>(Ws);          // 1
    k_deg<<<(NE + 255) / 256, 256>>>(dst, bidx);        // 2
    k_dinv<<<(NN + 255) / 256, 256>>>();                // 3
    k_gemm_tc<<<gemm_grid, 256, SM_TOTAL>>>(0, x);      // 4  <- ncu capture slot
    k_bsum<<<SCAN_NB, SCAN_T>>>();                      // 5
    k_bscan<<<1, 256>>>();                              // 6
    k_lscan<<<SCAN_NB, SCAN_T>>>();                     // 7
    k_fill<<<(NE + 255) / 256, 256>>>(src, dst);        // 8

    k_agg<<<agg_grid, 256>>>(0, bs);                    // 9
    k_fin<<<1, DH>>>(0, gammas, betas);
    for (int l = 1; l < NL; ++l) {
        k_gemm_tc<<<gemm_grid, 256, SM_TOTAL>>>(l, x);
        k_agg<<<agg_grid, 256>>>(l, bs + l * DH);
        k_fin<<<1, DH>>>(l, gammas + l * DH, betas + l * DH);
    }

    cudaMemsetAsync(d_out, 0, (size_t)NG * DH * sizeof(float));
    int pool_grid = (NN + 63) / 64;
    k_pool<<<pool_grid, 256>>>(bidx, out);
    k_div<<<(NG * DH + 255) / 256, 256>>>(out);
}